// round 1
// baseline (speedup 1.0000x reference)
#include <cuda_runtime.h>
#include <math.h>

// ComponentNN blend-MLP: 3x fused blend-GEMM layers.
// out[b,o] = sum_e blend[e,b] * ( sum_i w[e,o,i]*h[b,i] + bias[e,o] ), ELU between layers.
// Restructured as one GEMM per layer: K_total = E*d_in, A'[b, e*din+i] = blend[e,b]*h[b,i].
// fp32 math using packed fma.rn.f32x2 (2 FMAs/instr on Blackwell FP32 pipe).

#define TPB 128
#define BM 64
#define BN 64
#define BK 16
#define LDA 68   // padded smem row length in floats (multiple of 4 for aligned 16B reads)

typedef unsigned long long ull;

__device__ __forceinline__ ull pack2(float lo, float hi) {
    ull r; asm("mov.b64 %0, {%1,%2};" : "=l"(r) : "f"(lo), "f"(hi)); return r;
}
__device__ __forceinline__ void unpack2(ull v, float& lo, float& hi) {
    asm("mov.b64 {%0,%1}, %2;" : "=f"(lo), "=f"(hi) : "l"(v));
}
__device__ __forceinline__ void fma2(ull& d, ull a, ull b) {
    asm("fma.rn.f32x2 %0, %1, %2, %0;" : "+l"(d) : "l"(a), "l"(b));
}

// Intermediate activation scratch (no allocations allowed in kernel_launch).
__device__ float g_h1[1024 * 512];
__device__ float g_h2[1024 * 512];

__global__ __launch_bounds__(TPB) void blend_layer_kernel(
    const float* __restrict__ X,      // [M][K]      activations
    const float* __restrict__ W,      // [E][N][K]   expert weights
    const float* __restrict__ Bias,   // [E][N]
    const float* __restrict__ Blend,  // [E][M]
    float* __restrict__ Out,          // [M][N]
    int M, int N, int K, int doAct)
{
    __shared__ __align__(16) float As[BK][LDA];
    __shared__ __align__(16) float Bs[BK][LDA];

    const int tid = threadIdx.x;
    const int tx  = tid & 15;   // 0..15  -> 4 output cols each
    const int ty  = tid >> 4;   // 0..7   -> 8 output rows each
    const int m0  = blockIdx.y * BM;
    const int n0  = blockIdx.x * BN;

    // loader mapping: 64 rows x 16 cols tile = 256 float4; 128 threads -> 2 each
    const int lrow = tid >> 2;         // 0..31 (and +32)
    const int lcol = (tid & 3) << 2;   // 0,4,8,12

    const int tpe = K / BK;            // K-tiles per expert (480/16=30, 512/16=32)
    const int KT  = 8 * tpe;           // total K-tiles across experts

    const int ga0 = m0 + lrow, ga1 = ga0 + 32;
    const int gb0 = n0 + lrow, gb1 = gb0 + 32;

    ull acc[4][4];
    #pragma unroll
    for (int p = 0; p < 4; p++)
        #pragma unroll
        for (int j = 0; j < 4; j++) acc[p][j] = 0ull;

    const float4 z4 = make_float4(0.f, 0.f, 0.f, 0.f);
    float4 aR0, aR1, bR0, bR1;
    float  bl0, bl1;

    // prologue: stage tile (e=0, i0=0)
    aR0 = *reinterpret_cast<const float4*>(&X[(size_t)ga0 * K + lcol]);
    aR1 = *reinterpret_cast<const float4*>(&X[(size_t)ga1 * K + lcol]);
    bl0 = Blend[ga0];
    bl1 = Blend[ga1];
    bR0 = (gb0 < N) ? *reinterpret_cast<const float4*>(&W[(size_t)gb0 * K + lcol]) : z4;
    bR1 = (gb1 < N) ? *reinterpret_cast<const float4*>(&W[(size_t)gb1 * K + lcol]) : z4;

    int e = 0, io = 0;  // (expert, inner-k offset) of the staged tile

    for (int kt = 0; kt < KT; kt++) {
        __syncthreads();
        // store staged regs -> smem (transposed). Blend folded into A.
        As[lcol + 0][lrow]      = aR0.x * bl0;
        As[lcol + 1][lrow]      = aR0.y * bl0;
        As[lcol + 2][lrow]      = aR0.z * bl0;
        As[lcol + 3][lrow]      = aR0.w * bl0;
        As[lcol + 0][lrow + 32] = aR1.x * bl1;
        As[lcol + 1][lrow + 32] = aR1.y * bl1;
        As[lcol + 2][lrow + 32] = aR1.z * bl1;
        As[lcol + 3][lrow + 32] = aR1.w * bl1;
        Bs[lcol + 0][lrow]      = bR0.x;
        Bs[lcol + 1][lrow]      = bR0.y;
        Bs[lcol + 2][lrow]      = bR0.z;
        Bs[lcol + 3][lrow]      = bR0.w;
        Bs[lcol + 0][lrow + 32] = bR1.x;
        Bs[lcol + 1][lrow + 32] = bR1.y;
        Bs[lcol + 2][lrow + 32] = bR1.z;
        Bs[lcol + 3][lrow + 32] = bR1.w;
        __syncthreads();

        // prefetch next tile into regs (overlaps with compute below)
        if (kt + 1 < KT) {
            io += BK;
            if (io == K) { io = 0; e++; }
            const float* wbase = W + (size_t)e * N * K;
            aR0 = *reinterpret_cast<const float4*>(&X[(size_t)ga0 * K + io + lcol]);
            aR1 = *reinterpret_cast<const float4*>(&X[(size_t)ga1 * K + io + lcol]);
            bl0 = Blend[e * M + ga0];
            bl1 = Blend[e * M + ga1];
            bR0 = (gb0 < N) ? *reinterpret_cast<const float4*>(&wbase[(size_t)gb0 * K + io + lcol]) : z4;
            bR1 = (gb1 < N) ? *reinterpret_cast<const float4*>(&wbase[(size_t)gb1 * K + io + lcol]) : z4;
        }

        #pragma unroll
        for (int k = 0; k < BK; k++) {
            // A: 8 consecutive rows for this thread, as 4 packed row-pairs
            ulonglong2 aA = *reinterpret_cast<const ulonglong2*>(&As[k][ty * 8]);
            ulonglong2 aB = *reinterpret_cast<const ulonglong2*>(&As[k][ty * 8 + 4]);
            // B: 4 cols, broadcast into both halves
            float4 bv = *reinterpret_cast<const float4*>(&Bs[k][tx * 4]);
            ull b0 = pack2(bv.x, bv.x);
            ull b1 = pack2(bv.y, bv.y);
            ull b2 = pack2(bv.z, bv.z);
            ull b3 = pack2(bv.w, bv.w);
            fma2(acc[0][0], aA.x, b0); fma2(acc[0][1], aA.x, b1);
            fma2(acc[0][2], aA.x, b2); fma2(acc[0][3], aA.x, b3);
            fma2(acc[1][0], aA.y, b0); fma2(acc[1][1], aA.y, b1);
            fma2(acc[1][2], aA.y, b2); fma2(acc[1][3], aA.y, b3);
            fma2(acc[2][0], aB.x, b0); fma2(acc[2][1], aB.x, b1);
            fma2(acc[2][2], aB.x, b2); fma2(acc[2][3], aB.x, b3);
            fma2(acc[3][0], aB.y, b0); fma2(acc[3][1], aB.y, b1);
            fma2(acc[3][2], aB.y, b2); fma2(acc[3][3], aB.y, b3);
        }
    }

    // ---- epilogue ----
    float res[8][4];
    #pragma unroll
    for (int p = 0; p < 4; p++)
        #pragma unroll
        for (int j = 0; j < 4; j++)
            unpack2(acc[p][j], res[2 * p][j], res[2 * p + 1][j]);

    const int gr0 = m0 + ty * 8;
    const int gc0 = n0 + tx * 4;

    // blended bias: out += sum_e blend[e,b] * bias[e,o]
    #pragma unroll
    for (int ee = 0; ee < 8; ee++) {
        float be0 = (gc0 + 0 < N) ? Bias[ee * N + gc0 + 0] : 0.f;
        float be1 = (gc0 + 1 < N) ? Bias[ee * N + gc0 + 1] : 0.f;
        float be2 = (gc0 + 2 < N) ? Bias[ee * N + gc0 + 2] : 0.f;
        float be3 = (gc0 + 3 < N) ? Bias[ee * N + gc0 + 3] : 0.f;
        #pragma unroll
        for (int r = 0; r < 8; r++) {
            float bl = Blend[ee * M + gr0 + r];
            res[r][0] += bl * be0;
            res[r][1] += bl * be1;
            res[r][2] += bl * be2;
            res[r][3] += bl * be3;
        }
    }

    if (doAct) {
        #pragma unroll
        for (int r = 0; r < 8; r++)
            #pragma unroll
            for (int j = 0; j < 4; j++) {
                float v = res[r][j];
                res[r][j] = (v > 0.f) ? v : expm1f(v);
            }
    }

    if ((N & 3) == 0) {
        #pragma unroll
        for (int r = 0; r < 8; r++) {
            float4 v = make_float4(res[r][0], res[r][1], res[r][2], res[r][3]);
            *reinterpret_cast<float4*>(&Out[(size_t)(gr0 + r) * N + gc0]) = v;
        }
    } else {
        #pragma unroll
        for (int r = 0; r < 8; r++)
            #pragma unroll
            for (int j = 0; j < 4; j++)
                if (gc0 + j < N) Out[(size_t)(gr0 + r) * N + gc0 + j] = res[r][j];
    }
}

extern "C" void kernel_launch(void* const* d_in, const int* in_sizes, int n_in,
                              void* d_out, int out_size) {
    const float* x  = (const float*)d_in[0];  // [1024,480]
    const float* wb = (const float*)d_in[1];  // [8,1024]
    const float* w0 = (const float*)d_in[2];  // [8,512,480]
    const float* b0 = (const float*)d_in[3];  // [8,512]
    const float* w1 = (const float*)d_in[4];  // [8,512,512]
    const float* b1 = (const float*)d_in[5];  // [8,512]
    const float* w2 = (const float*)d_in[6];  // [8,311,512]
    const float* b2 = (const float*)d_in[7];  // [8,311]
    float* out = (float*)d_out;               // [1024,311]

    float *h1 = nullptr, *h2 = nullptr;
    cudaGetSymbolAddress((void**)&h1, g_h1);
    cudaGetSymbolAddress((void**)&h2, g_h2);

    const int M = 1024;
    dim3 block(TPB);
    blend_layer_kernel<<<dim3(512 / BN, M / BM), block>>>(x,  w0, b0, wb, h1,  M, 512, 480, 1);
    blend_layer_kernel<<<dim3(512 / BN, M / BM), block>>>(h1, w1, b1, wb, h2,  M, 512, 512, 1);
    blend_layer_kernel<<<dim3((311 + BN - 1) / BN, M / BM), block>>>(h2, w2, b2, wb, out, M, 311, 512, 0);
}

// round 2
// speedup vs baseline: 1.0034x; 1.0034x over previous
#include <cuda_runtime.h>
#include <math.h>

// ComponentNN blend-MLP: 3x fused blend-GEMM layers.
// out[b,o] = sum_e blend[e,b] * ( sum_i w[e,o,i]*h[b,i] + bias[e,o] ), ELU between layers.
// Restructured as one GEMM per layer: K_total = E*d_in, A'[b, e*din+i] = blend[e,b]*h[b,i].
// fp32 math using packed fma.rn.f32x2 (2 FMAs/instr on Blackwell FP32 pipe).

#define TPB 128
#define BM 64
#define BN 64
#define BK 16
#define LDA 68   // padded smem row length in floats (multiple of 4 for aligned 16B reads)

typedef unsigned long long ull;

__device__ __forceinline__ ull pack2(float lo, float hi) {
    ull r; asm("mov.b64 %0, {%1,%2};" : "=l"(r) : "f"(lo), "f"(hi)); return r;
}
__device__ __forceinline__ void unpack2(ull v, float& lo, float& hi) {
    asm("mov.b64 {%0,%1}, %2;" : "=f"(lo), "=f"(hi) : "l"(v));
}
__device__ __forceinline__ void fma2(ull& d, ull a, ull b) {
    asm("fma.rn.f32x2 %0, %1, %2, %0;" : "+l"(d) : "l"(a), "l"(b));
}

// Intermediate activation scratch (no allocations allowed in kernel_launch).
__device__ float g_h1[1024 * 512];
__device__ float g_h2[1024 * 512];

__global__ __launch_bounds__(TPB) void blend_layer_kernel(
    const float* __restrict__ X,      // [M][K]      activations
    const float* __restrict__ W,      // [E][N][K]   expert weights
    const float* __restrict__ Bias,   // [E][N]
    const float* __restrict__ Blend,  // [E][M]
    float* __restrict__ Out,          // [M][N]
    int M, int N, int K, int doAct)
{
    __shared__ __align__(16) float As[BK][LDA];
    __shared__ __align__(16) float Bs[BK][LDA];

    const int tid = threadIdx.x;
    const int tx  = tid & 15;   // 0..15  -> 4 output cols each
    const int ty  = tid >> 4;   // 0..7   -> 8 output rows each
    const int m0  = blockIdx.y * BM;
    const int n0  = blockIdx.x * BN;

    // loader mapping: 64 rows x 16 cols tile = 256 float4; 128 threads -> 2 each
    const int lrow = tid >> 2;         // 0..31 (and +32)
    const int lcol = (tid & 3) << 2;   // 0,4,8,12

    const int tpe = K / BK;            // K-tiles per expert (480/16=30, 512/16=32)
    const int KT  = 8 * tpe;           // total K-tiles across experts

    const int ga0 = m0 + lrow, ga1 = ga0 + 32;
    const int gb0 = n0 + lrow, gb1 = gb0 + 32;

    ull acc[4][4];
    #pragma unroll
    for (int p = 0; p < 4; p++)
        #pragma unroll
        for (int j = 0; j < 4; j++) acc[p][j] = 0ull;

    const float4 z4 = make_float4(0.f, 0.f, 0.f, 0.f);
    float4 aR0, aR1, bR0, bR1;
    float  bl0, bl1;

    // prologue: stage tile (e=0, i0=0)
    aR0 = *reinterpret_cast<const float4*>(&X[(size_t)ga0 * K + lcol]);
    aR1 = *reinterpret_cast<const float4*>(&X[(size_t)ga1 * K + lcol]);
    bl0 = Blend[ga0];
    bl1 = Blend[ga1];
    bR0 = (gb0 < N) ? *reinterpret_cast<const float4*>(&W[(size_t)gb0 * K + lcol]) : z4;
    bR1 = (gb1 < N) ? *reinterpret_cast<const float4*>(&W[(size_t)gb1 * K + lcol]) : z4;

    int e = 0, io = 0;  // (expert, inner-k offset) of the staged tile

    for (int kt = 0; kt < KT; kt++) {
        __syncthreads();
        // store staged regs -> smem (transposed). Blend folded into A.
        As[lcol + 0][lrow]      = aR0.x * bl0;
        As[lcol + 1][lrow]      = aR0.y * bl0;
        As[lcol + 2][lrow]      = aR0.z * bl0;
        As[lcol + 3][lrow]      = aR0.w * bl0;
        As[lcol + 0][lrow + 32] = aR1.x * bl1;
        As[lcol + 1][lrow + 32] = aR1.y * bl1;
        As[lcol + 2][lrow + 32] = aR1.z * bl1;
        As[lcol + 3][lrow + 32] = aR1.w * bl1;
        Bs[lcol + 0][lrow]      = bR0.x;
        Bs[lcol + 1][lrow]      = bR0.y;
        Bs[lcol + 2][lrow]      = bR0.z;
        Bs[lcol + 3][lrow]      = bR0.w;
        Bs[lcol + 0][lrow + 32] = bR1.x;
        Bs[lcol + 1][lrow + 32] = bR1.y;
        Bs[lcol + 2][lrow + 32] = bR1.z;
        Bs[lcol + 3][lrow + 32] = bR1.w;
        __syncthreads();

        // prefetch next tile into regs (overlaps with compute below)
        if (kt + 1 < KT) {
            io += BK;
            if (io == K) { io = 0; e++; }
            const float* wbase = W + (size_t)e * N * K;
            aR0 = *reinterpret_cast<const float4*>(&X[(size_t)ga0 * K + io + lcol]);
            aR1 = *reinterpret_cast<const float4*>(&X[(size_t)ga1 * K + io + lcol]);
            bl0 = Blend[e * M + ga0];
            bl1 = Blend[e * M + ga1];
            bR0 = (gb0 < N) ? *reinterpret_cast<const float4*>(&wbase[(size_t)gb0 * K + io + lcol]) : z4;
            bR1 = (gb1 < N) ? *reinterpret_cast<const float4*>(&wbase[(size_t)gb1 * K + io + lcol]) : z4;
        }

        #pragma unroll
        for (int k = 0; k < BK; k++) {
            // A: 8 consecutive rows for this thread, as 4 packed row-pairs
            ulonglong2 aA = *reinterpret_cast<const ulonglong2*>(&As[k][ty * 8]);
            ulonglong2 aB = *reinterpret_cast<const ulonglong2*>(&As[k][ty * 8 + 4]);
            // B: 4 cols, broadcast into both halves
            float4 bv = *reinterpret_cast<const float4*>(&Bs[k][tx * 4]);
            ull b0 = pack2(bv.x, bv.x);
            ull b1 = pack2(bv.y, bv.y);
            ull b2 = pack2(bv.z, bv.z);
            ull b3 = pack2(bv.w, bv.w);
            fma2(acc[0][0], aA.x, b0); fma2(acc[0][1], aA.x, b1);
            fma2(acc[0][2], aA.x, b2); fma2(acc[0][3], aA.x, b3);
            fma2(acc[1][0], aA.y, b0); fma2(acc[1][1], aA.y, b1);
            fma2(acc[1][2], aA.y, b2); fma2(acc[1][3], aA.y, b3);
            fma2(acc[2][0], aB.x, b0); fma2(acc[2][1], aB.x, b1);
            fma2(acc[2][2], aB.x, b2); fma2(acc[2][3], aB.x, b3);
            fma2(acc[3][0], aB.y, b0); fma2(acc[3][1], aB.y, b1);
            fma2(acc[3][2], aB.y, b2); fma2(acc[3][3], aB.y, b3);
        }
    }

    // ---- epilogue ----
    float res[8][4];
    #pragma unroll
    for (int p = 0; p < 4; p++)
        #pragma unroll
        for (int j = 0; j < 4; j++)
            unpack2(acc[p][j], res[2 * p][j], res[2 * p + 1][j]);

    const int gr0 = m0 + ty * 8;
    const int gc0 = n0 + tx * 4;

    // blended bias: out += sum_e blend[e,b] * bias[e,o]
    #pragma unroll
    for (int ee = 0; ee < 8; ee++) {
        float be0 = (gc0 + 0 < N) ? Bias[ee * N + gc0 + 0] : 0.f;
        float be1 = (gc0 + 1 < N) ? Bias[ee * N + gc0 + 1] : 0.f;
        float be2 = (gc0 + 2 < N) ? Bias[ee * N + gc0 + 2] : 0.f;
        float be3 = (gc0 + 3 < N) ? Bias[ee * N + gc0 + 3] : 0.f;
        #pragma unroll
        for (int r = 0; r < 8; r++) {
            float bl = Blend[ee * M + gr0 + r];
            res[r][0] += bl * be0;
            res[r][1] += bl * be1;
            res[r][2] += bl * be2;
            res[r][3] += bl * be3;
        }
    }

    if (doAct) {
        #pragma unroll
        for (int r = 0; r < 8; r++)
            #pragma unroll
            for (int j = 0; j < 4; j++) {
                float v = res[r][j];
                res[r][j] = (v > 0.f) ? v : expm1f(v);
            }
    }

    if ((N & 3) == 0) {
        #pragma unroll
        for (int r = 0; r < 8; r++) {
            float4 v = make_float4(res[r][0], res[r][1], res[r][2], res[r][3]);
            *reinterpret_cast<float4*>(&Out[(size_t)(gr0 + r) * N + gc0]) = v;
        }
    } else {
        #pragma unroll
        for (int r = 0; r < 8; r++)
            #pragma unroll
            for (int j = 0; j < 4; j++)
                if (gc0 + j < N) Out[(size_t)(gr0 + r) * N + gc0 + j] = res[r][j];
    }
}

extern "C" void kernel_launch(void* const* d_in, const int* in_sizes, int n_in,
                              void* d_out, int out_size) {
    const float* x  = (const float*)d_in[0];  // [1024,480]
    const float* wb = (const float*)d_in[1];  // [8,1024]
    const float* w0 = (const float*)d_in[2];  // [8,512,480]
    const float* b0 = (const float*)d_in[3];  // [8,512]
    const float* w1 = (const float*)d_in[4];  // [8,512,512]
    const float* b1 = (const float*)d_in[5];  // [8,512]
    const float* w2 = (const float*)d_in[6];  // [8,311,512]
    const float* b2 = (const float*)d_in[7];  // [8,311]
    float* out = (float*)d_out;               // [1024,311]

    float *h1 = nullptr, *h2 = nullptr;
    cudaGetSymbolAddress((void**)&h1, g_h1);
    cudaGetSymbolAddress((void**)&h2, g_h2);

    const int M = 1024;
    dim3 block(TPB);
    blend_layer_kernel<<<dim3(512 / BN, M / BM), block>>>(x,  w0, b0, wb, h1,  M, 512, 480, 1);
    blend_layer_kernel<<<dim3(512 / BN, M / BM), block>>>(h1, w1, b1, wb, h2,  M, 512, 512, 1);
    blend_layer_kernel<<<dim3((311 + BN - 1) / BN, M / BM), block>>>(h2, w2, b2, wb, out, M, 311, 512, 0);
}